// round 12
// baseline (speedup 1.0000x reference)
#include <cuda_runtime.h>
#include <cuda_fp16.h>
#include <cstdint>

// ============================================================================
// StyleGAN2 ModulatedConv2D via Winograd F(2x2,3x3) + HMMA mma.sync GEMMs.
//   U[xi][co][ci] = G w G^T            (weight transform, fp16, 16 mats)
//   D[xi][tg][ci] = B^T (s*x patch) B  (input transform + modulation, fp16)
//   M[xi][tg][co] = D[xi] @ U[xi]^T    (16 GEMMs, HMMA fp16->fp32, M fp16)
//   out(2x2 tile) = demod*RC_W * A^T M A
// R12: gemm does 2 xi per CTA (32-chunk K loop, mid-loop acc dump) and a
//      4-stage cp.async pipeline (prefetch distance 3) to amortize CTA
//      fixed costs; numerics identical to R11.
// ============================================================================

#define CIN     512
#define COUT    512
#define LATENTD 512
#define NBATCH  8
#define HW      4096
#define NTILES  8192              // 8 * 32 * 32
#define NCHP    16                // K chunks per xi (512/32)
#define NCHT    32                // chunks per CTA (2 xi)
#define PITCH   80                // 64B payload + 16B pad
#define A_BYTES (128 * PITCH)     // 10240
#define STG_B   (2 * A_BYTES)     // 20480
#define SMEM_SZ (4 * STG_B)       // 81920 dynamic (gemm, 4 stages)

#define XT_PITCH 35               // odd float pitch: conflict-free ld+st
#define XT_SMEM  (10 * 64 * XT_PITCH * 4)   // 89600 dynamic (xT)

#define RC_W 0.014731391274719738f   // 1/sqrt(9*512)
#define RC_S 0.04419417382415922f    // 1/sqrt(512)

__device__ float g_style[NBATCH * CIN];
__device__ float g_demod[NBATCH * COUT];
__device__ float g_wsq[CIN * COUT];
__device__ __align__(16) __half g_U[(size_t)16 * COUT * CIN];    // [xi][co][ci]
__device__ __align__(16) __half g_D[(size_t)16 * NTILES * CIN];  // [xi][tg][ci]
__device__ __align__(16) __half g_M[(size_t)16 * NTILES * COUT]; // [xi][tg][co]

// ---------------- PTX helpers ----------------------------------------------
__device__ __forceinline__ uint32_t smem_u32(const void* p) {
    uint32_t a;
    asm("{ .reg .u64 t; cvta.to.shared.u64 t, %1; cvt.u32.u64 %0, t; }"
        : "=r"(a) : "l"(p));
    return a;
}
__device__ __forceinline__ void cp16(uint32_t s, const void* g) {
    asm volatile("cp.async.cg.shared.global [%0], [%1], 16;"
                 :: "r"(s), "l"(g) : "memory");
}
#define CP_COMMIT() asm volatile("cp.async.commit_group;" ::: "memory")
#define CP_WAIT2()  asm volatile("cp.async.wait_group 2;" ::: "memory")
#define CP_WAIT0()  asm volatile("cp.async.wait_group 0;" ::: "memory")

#define LDSM4(r, addr) \
    asm volatile("ldmatrix.sync.aligned.m8n8.x4.shared.b16 {%0,%1,%2,%3}, [%4];" \
                 : "=r"((r)[0]), "=r"((r)[1]), "=r"((r)[2]), "=r"((r)[3]) \
                 : "r"(addr))

#define MMA16816(d, a, b0, b1) \
    asm volatile("mma.sync.aligned.m16n8k16.row.col.f32.f16.f16.f32 " \
                 "{%0,%1,%2,%3},{%4,%5,%6,%7},{%8,%9},{%0,%1,%2,%3};" \
                 : "+f"((d)[0]), "+f"((d)[1]), "+f"((d)[2]), "+f"((d)[3]) \
                 : "r"((a)[0]), "r"((a)[1]), "r"((a)[2]), "r"((a)[3]), \
                   "r"(b0), "r"(b1))

// ---------------- style / demod (validated since R3) ------------------------
__global__ void style_k(const float* __restrict__ dl,
                        const float* __restrict__ mw,
                        const float* __restrict__ mb) {
    const int n = blockIdx.x, ci = threadIdx.x;
    __shared__ float dls[LATENTD];
    dls[ci] = dl[n * LATENTD + ci];
    __syncthreads();
    float acc = 0.0f;
#pragma unroll 8
    for (int l = 0; l < LATENTD; l++) acc += dls[l] * mw[l * CIN + ci];
    g_style[n * CIN + ci] = acc * RC_S + mb[ci] + 1.0f;
}

__global__ void demod_k() {
    const int n = blockIdx.x, co = threadIdx.x;
    __shared__ float s2[CIN];
    float sv = g_style[n * CIN + co];
    s2[co] = sv * sv;
    __syncthreads();
    float acc = 0.0f;
#pragma unroll 8
    for (int ci = 0; ci < CIN; ci++) acc += s2[ci] * g_wsq[ci * COUT + co];
    g_demod[n * COUT + co] = rsqrtf(acc * (RC_W * RC_W) + 1e-8f);
}

// ---------------- weight transform: U = G w G^T (+ wsq) ---------------------
__global__ void wT_k(const float* __restrict__ w) {
    __shared__ float sw[9][32][33];
    const int tx = threadIdx.x, ty = threadIdx.y;
    const int ci0 = blockIdx.x * 32, co0 = blockIdx.y * 32;
#pragma unroll
    for (int kk = 0; kk < 9; kk++)
#pragma unroll
        for (int r = 0; r < 4; r++)
            sw[kk][ty + r * 8][tx] =
                w[((size_t)kk * CIN + ci0 + ty + r * 8) * COUT + co0 + tx];
    __syncthreads();
#pragma unroll
    for (int q = 0; q < 4; q++) {
        const int col = ty + q * 8;
        const int ci = ci0 + tx, co = co0 + col;
        float g[9], sq = 0.0f;
#pragma unroll
        for (int kk = 0; kk < 9; kk++) {
            g[kk] = sw[kk][tx][col];
            sq += g[kk] * g[kk];
        }
        g_wsq[ci * COUT + co] = sq;
        float t[4][3];
#pragma unroll
        for (int c = 0; c < 3; c++) {
            const float a = g[c], b = g[3 + c], d = g[6 + c];
            t[0][c] = a;
            t[1][c] = 0.5f * (a + b + d);
            t[2][c] = 0.5f * (a - b + d);
            t[3][c] = d;
        }
#pragma unroll
        for (int r = 0; r < 4; r++) {
            const float a = t[r][0], b = t[r][1], d = t[r][2];
            float u[4];
            u[0] = a;
            u[1] = 0.5f * (a + b + d);
            u[2] = 0.5f * (a - b + d);
            u[3] = d;
#pragma unroll
            for (int c = 0; c < 4; c++)
                g_U[((size_t)(r * 4 + c) * COUT + co) * CIN + ci] =
                    __float2half(u[c]);
        }
    }
}

// ---------------- input transform: D = B^T (s*d) B ---------------------------
__global__ void xT_k(const float* __restrict__ x) {
    extern __shared__ __align__(16) float si[];   // [10 rows][64 px][pitch 35]
    const int tid = threadIdx.x;
    const int ci0 = blockIdx.x * 32, by = blockIdx.y, n = blockIdx.z;

    const int px = tid & 63, sub = tid >> 6;
#pragma unroll
    for (int it = 0; it < 80; it++) {
        const int pair = it * 4 + sub;            // 0..319
        const int row = pair >> 5, ci_l = pair & 31;
        const int gy = 8 * by - 1 + row;
        const float v = ((unsigned)gy < 64u)
            ? x[((size_t)(n * CIN + ci0 + ci_l) * 64 + gy) * 64 + px] : 0.0f;
        si[(row * 64 + px) * XT_PITCH + ci_l] = v;
    }
    __syncthreads();

    const int cp = tid & 15;
    const int tgrp = tid >> 4;
    const float sv0 = g_style[n * CIN + ci0 + 2 * cp];
    const float sv1 = g_style[n * CIN + ci0 + 2 * cp + 1];

#pragma unroll
    for (int ty_l = 0; ty_l < 4; ty_l++) {
#pragma unroll
        for (int tt = 0; tt < 2; tt++) {
            const int tx = tgrp + tt * 16;
            const int tg = n * 1024 + (4 * by + ty_l) * 32 + tx;
            float d0[4][4], d1[4][4];
#pragma unroll
            for (int i = 0; i < 4; i++)
#pragma unroll
                for (int j = 0; j < 4; j++) {
                    const int pxx = 2 * tx - 1 + j;
                    if ((unsigned)pxx < 64u) {
                        const float* p =
                            &si[((2 * ty_l + i) * 64 + pxx) * XT_PITCH + 2 * cp];
                        d0[i][j] = p[0] * sv0;
                        d1[i][j] = p[1] * sv1;
                    } else { d0[i][j] = 0.0f; d1[i][j] = 0.0f; }
                }
            float e0[4][4], e1[4][4];
#pragma unroll
            for (int j = 0; j < 4; j++) {
                e0[0][j] = d0[0][j] - d0[2][j];  e1[0][j] = d1[0][j] - d1[2][j];
                e0[1][j] = d0[1][j] + d0[2][j];  e1[1][j] = d1[1][j] + d1[2][j];
                e0[2][j] = d0[2][j] - d0[1][j];  e1[2][j] = d1[2][j] - d1[1][j];
                e0[3][j] = d0[1][j] - d0[3][j];  e1[3][j] = d1[1][j] - d1[3][j];
            }
            __half* dst = &g_D[(size_t)tg * CIN + ci0 + 2 * cp];
#pragma unroll
            for (int i = 0; i < 4; i++) {
                float f0[4], f1[4];
                f0[0] = e0[i][0] - e0[i][2];  f1[0] = e1[i][0] - e1[i][2];
                f0[1] = e0[i][1] + e0[i][2];  f1[1] = e1[i][1] + e1[i][2];
                f0[2] = e0[i][2] - e0[i][1];  f1[2] = e1[i][2] - e1[i][1];
                f0[3] = e0[i][1] - e0[i][3];  f1[3] = e1[i][1] - e1[i][3];
#pragma unroll
                for (int j = 0; j < 4; j++)
                    *(__half2*)(dst + (size_t)(i * 4 + j) * NTILES * CIN) =
                        __floats2half2_rn(f0[j], f1[j]);
            }
        }
    }
}

// ---------------- GEMMs: M[xi] = D[xi] @ U[xi]^T, 2 xi per CTA ---------------
__global__ void __launch_bounds__(256, 2) gemm_k() {
    extern __shared__ __align__(128) char dsm[];

    const int tid = threadIdx.x;
    const int wid = tid >> 5, lane = tid & 31;
    const int xi0 = blockIdx.z * 2;
    const int co0 = blockIdx.x * 128;
    const int m0 = blockIdx.y * 128;
    const int wm = (wid & 1) * 64;
    const int wn = (wid >> 1) * 32;

    const uint32_t sbase = smem_u32(dsm);

    const int arow = tid >> 1, ahalf = tid & 1;
    const uint32_t rc_st = (uint32_t)(arow * PITCH + ahalf * 32);
    const __half* ga_base =
        g_D + ((size_t)xi0 * NTILES + m0 + arow) * CIN + ahalf * 16;
    const __half* gb_base =
        g_U + ((size_t)xi0 * COUT + co0 + arow) * CIN + ahalf * 16;

    auto issue = [&](int j, int st) {
        const size_t xoffA = (j >> 4) ? (size_t)NTILES * CIN : 0;
        const size_t xoffB = (j >> 4) ? (size_t)COUT * CIN : 0;
        const int k0 = (j & 15) << 5;
        const __half* ga = ga_base + xoffA + k0;
        const uint32_t ab = sbase + st * STG_B + rc_st;
        cp16(ab, ga);
        cp16(ab + 16, ga + 8);
        const __half* gb = gb_base + xoffB + k0;
        const uint32_t bb = ab + A_BYTES;
        cp16(bb, gb);
        cp16(bb + 16, gb + 8);
    };

    uint32_t a_off[4], b_off[2];
#pragma unroll
    for (int mt = 0; mt < 4; mt++)
        a_off[mt] = (uint32_t)((wm + mt * 16 + (lane & 15)) * PITCH +
                               (lane >> 4) * 16);
#pragma unroll
    for (int bt = 0; bt < 2; bt++)
        b_off[bt] = (uint32_t)(
            (wn + bt * 16 + (lane & 7) + ((lane >> 4) & 1) * 8) * PITCH +
            ((lane >> 3) & 1) * 16) + A_BYTES;

    float acc[4][4][4];
#pragma unroll
    for (int mt = 0; mt < 4; mt++)
#pragma unroll
        for (int nt = 0; nt < 4; nt++)
#pragma unroll
            for (int r = 0; r < 4; r++) acc[mt][nt][r] = 0.0f;

    // epilogue/dump: write acc -> g_M[xi], then zero acc
    auto dump = [&](int xi) {
        __half* mbp = g_M + (size_t)xi * NTILES * COUT;
#pragma unroll
        for (int nt = 0; nt < 4; nt++) {
            const int col = co0 + wn + nt * 8 + (lane & 3) * 2;
#pragma unroll
            for (int mt = 0; mt < 4; mt++) {
                const int row = m0 + wm + mt * 16 + (lane >> 2);
                *(__half2*)&mbp[(size_t)row * COUT + col] =
                    __floats2half2_rn(acc[mt][nt][0], acc[mt][nt][1]);
                *(__half2*)&mbp[(size_t)(row + 8) * COUT + col] =
                    __floats2half2_rn(acc[mt][nt][2], acc[mt][nt][3]);
                acc[mt][nt][0] = 0.0f; acc[mt][nt][1] = 0.0f;
                acc[mt][nt][2] = 0.0f; acc[mt][nt][3] = 0.0f;
            }
        }
    };

    issue(0, 0); CP_COMMIT();
    issue(1, 1); CP_COMMIT();
    issue(2, 2); CP_COMMIT();

    for (int i = 0; i < NCHT; i++) {
        CP_WAIT2();               // chunk i's group complete (3 in flight)
        __syncthreads();          // all warps done reading stage (i+3)&3's prev
        if (i == NCHP) dump(xi0); // xi0 complete after iter NCHP-1
        const uint32_t stB = sbase + (i & 3) * STG_B;
#pragma unroll
        for (int ks = 0; ks < 2; ks++) {
            uint32_t af[4][4], bf[2][4];
#pragma unroll
            for (int mt = 0; mt < 4; mt++)
                LDSM4(af[mt], stB + a_off[mt] + ks * 32);
#pragma unroll
            for (int bt = 0; bt < 2; bt++)
                LDSM4(bf[bt], stB + b_off[bt] + ks * 32);
#pragma unroll
            for (int mt = 0; mt < 4; mt++) {
                MMA16816(acc[mt][0], af[mt], bf[0][0], bf[0][1]);
                MMA16816(acc[mt][1], af[mt], bf[0][2], bf[0][3]);
                MMA16816(acc[mt][2], af[mt], bf[1][0], bf[1][1]);
                MMA16816(acc[mt][3], af[mt], bf[1][2], bf[1][3]);
            }
        }
        if (i + 3 < NCHT) issue(i + 3, (i + 3) & 3);
        CP_COMMIT();
    }
    CP_WAIT0();
    dump(xi0 + 1);
}

// ---------------- output transform: out = demod*RC_W * A^T M A ---------------
__global__ void outT_k(float* __restrict__ out) {
    __shared__ float sm[16 * 32 * 17];  // [xi][t][c], c stride 17
    const int tid = threadIdx.x;
    const int co0 = blockIdx.x * 16, ty = blockIdx.y, n = blockIdx.z;
    const int tg0 = n * 1024 + ty * 32;

    for (int idx = tid; idx < 16 * 32 * 2; idx += 256) {
        const int c8 = idx & 1, t = (idx >> 1) & 31, xi = idx >> 6;
        const uint4 v = *(const uint4*)&g_M[
            ((size_t)xi * NTILES + tg0 + t) * COUT + co0 + c8 * 8];
        float* s = &sm[(xi * 32 + t) * 17 + c8 * 8];
        float2 p;
        p = __half22float2(*(__half2*)&v.x); s[0] = p.x; s[1] = p.y;
        p = __half22float2(*(__half2*)&v.y); s[2] = p.x; s[3] = p.y;
        p = __half22float2(*(__half2*)&v.z); s[4] = p.x; s[5] = p.y;
        p = __half22float2(*(__half2*)&v.w); s[6] = p.x; s[7] = p.y;
    }
    __syncthreads();

    const int t = tid & 31;
    const int cgrp = tid >> 5;
#pragma unroll
    for (int cc = 0; cc < 2; cc++) {
        const int c = cgrp + cc * 8;
        const int co = co0 + c;
        float m[16];
#pragma unroll
        for (int xi = 0; xi < 16; xi++) m[xi] = sm[(xi * 32 + t) * 17 + c];
        float g0[4], g1[4];
#pragma unroll
        for (int v = 0; v < 4; v++) {
            g0[v] = m[v] + m[4 + v] + m[8 + v];
            g1[v] = m[4 + v] - m[8 + v] - m[12 + v];
        }
        const float dm = g_demod[n * COUT + co] * RC_W;
        const float y00 = (g0[0] + g0[1] + g0[2]) * dm;
        const float y01 = (g0[1] - g0[2] - g0[3]) * dm;
        const float y10 = (g1[0] + g1[1] + g1[2]) * dm;
        const float y11 = (g1[1] - g1[2] - g1[3]) * dm;
        float* ob = out + (((size_t)(n * COUT + co) * 64 + 2 * ty) * 64 + 2 * t);
        *(float2*)ob        = make_float2(y00, y01);
        *(float2*)(ob + 64) = make_float2(y10, y11);
    }
}

// ---------------- launch -----------------------------------------------------
extern "C" void kernel_launch(void* const* d_in, const int* in_sizes, int n_in,
                              void* d_out, int out_size) {
    const float* x  = (const float*)d_in[0];   // [8,512,64,64]
    const float* dl = (const float*)d_in[1];   // [8,512]
    const float* w  = (const float*)d_in[2];   // [3,3,512,512]
    const float* mw = (const float*)d_in[3];   // [512,512]
    const float* mb = (const float*)d_in[4];   // [512]
    float* out = (float*)d_out;                // [8,512,64,64]

    cudaFuncSetAttribute(gemm_k, cudaFuncAttributeMaxDynamicSharedMemorySize,
                         SMEM_SZ);
    cudaFuncSetAttribute(xT_k, cudaFuncAttributeMaxDynamicSharedMemorySize,
                         XT_SMEM);

    style_k<<<NBATCH, 512>>>(dl, mw, mb);
    wT_k<<<dim3(CIN / 32, COUT / 32), dim3(32, 8)>>>(w);
    demod_k<<<NBATCH, 512>>>();
    xT_k<<<dim3(CIN / 32, 8, NBATCH), 256, XT_SMEM>>>(x);
    gemm_k<<<dim3(COUT / 128, NTILES / 128, 8), 256, SMEM_SZ>>>();
    outT_k<<<dim3(COUT / 16, 32, NBATCH), 256>>>(out);
}